// round 15
// baseline (speedup 1.0000x reference)
#include <cuda_runtime.h>
#include <math.h>

#define NN 50000
#define EE 800000
#define GG 256
#define NB_AGG 6250   /* ceil(NN/8)    */
#define NB1    49     /* ceil(NN/1024) */
#define NB_MLP 196    /* ceil(NN/256)  */
#define NB_MT  784    /* 196 * 4 towers */
#define NB_PQ  1563   /* ceil(NN/32)   */
#define MT_PAD 33

typedef unsigned long long u64;

// ---- packed f32x2 helpers ----
__device__ __forceinline__ u64 pk2(float lo, float hi) {
    u64 r; asm("mov.b64 %0, {%1, %2};" : "=l"(r) : "f"(lo), "f"(hi)); return r;
}
__device__ __forceinline__ void upk2(u64 v, float& lo, float& hi) {
    asm("mov.b64 {%0, %1}, %2;" : "=f"(lo), "=f"(hi) : "l"(v));
}
__device__ __forceinline__ void fma2(u64& d, u64 a, u64 b) {
    asm("fma.rn.f32x2 %0, %1, %2, %0;" : "+l"(d) : "l"(a), "l"(b));
}
__device__ __forceinline__ void add2(u64& d, u64 a) {
    asm("add.rn.f32x2 %0, %1, %0;" : "+l"(d) : "l"(a));
}

// ---------------- device scratch ----------------
__device__ float g_H[NN * 32];
__device__ float g_O[NN * 32];
__device__ float g_OT[NN * 32];      // tower-output staging (pre-lin)
__device__ float g_P[NN * 128];
__device__ float g_Q[NN * 128];
__device__ float g_AGG[(size_t)NN * 512];
__device__ float g_Etab[4 * 128];
__device__ int   g_cnt[NN];          // statically zero; self-restored by k_scan
__device__ int   g_rowptr[NN + 1];
__device__ int   g_cursor[NN];
__device__ int   g_pack[EE];
__device__ float g_bnacc[64];        // statically zero; self-restored by k_lin
__device__ float g_bnAB[64];
__device__ float g_pool[GG * 32];    // zeroed by k_scan each run
__device__ int   g_done;             // statically zero; self-restored by k_lin

// ---------------- setup kernels ----------------
__global__ void k_hinit(const int* __restrict__ x, const float* __restrict__ node_emb) {
    int i = blockIdx.x * blockDim.x + threadIdx.x;
    if (i >= NN * 32) return;
    int n = i >> 5, f = i & 31;
    g_H[i] = node_emb[x[n] * 32 + f];
}

__global__ void k_count(const int* __restrict__ ei) {
    int e = blockIdx.x * blockDim.x + threadIdx.x;
    if (e < EE) atomicAdd(&g_cnt[ei[EE + e]], 1);
}

// single-block shuffle scan over 49 chunks; zeroes cnt (for next replay) + pool
__global__ void __launch_bounds__(1024) k_scan() {
    __shared__ int swarp[32];
    __shared__ int s_carry;
    int t = threadIdx.x, lane = t & 31, wid = t >> 5;
    if (t == 0) s_carry = 0;
    for (int i = t; i < GG * 32; i += 1024) g_pool[i] = 0.f;
    __syncthreads();
    for (int chunk = 0; chunk < NB1; chunk++) {
        int i = chunk * 1024 + t;
        int v = (i < NN) ? g_cnt[i] : 0;
        if (i < NN) g_cnt[i] = 0;
        int x = v;
#pragma unroll
        for (int off = 1; off < 32; off <<= 1) {
            int y = __shfl_up_sync(0xffffffffu, x, off);
            if (lane >= off) x += y;
        }
        if (lane == 31) swarp[wid] = x;
        __syncthreads();
        if (wid == 0) {
            int w = swarp[lane];
#pragma unroll
            for (int off = 1; off < 32; off <<= 1) {
                int y = __shfl_up_sync(0xffffffffu, w, off);
                if (lane >= off) w += y;
            }
            swarp[lane] = w;
        }
        __syncthreads();
        int excl = s_carry + (wid ? swarp[wid - 1] : 0) + x - v;
        if (i < NN) { g_rowptr[i] = excl; g_cursor[i] = excl; }
        __syncthreads();
        if (t == 1023) s_carry += swarp[31];
        __syncthreads();
    }
    if (t == 0) g_rowptr[NN] = EE;
}

__global__ void k_scatter(const int* __restrict__ ei, const int* __restrict__ eattr) {
    int e = blockIdx.x * blockDim.x + threadIdx.x;
    if (e >= EE) return;
    int src = ei[e];
    int dst = ei[EE + e];
    int at  = eattr[e];
    int pos = atomicAdd(&g_cursor[dst], 1);
    g_pack[pos] = src | (at << 16);
}

// ---------------- per-layer kernels ----------------
// k_pq: (block0: Etab) + (all blocks: BN-apply+relu of prev g_O -> h, P=h@A, Q=h@B)
__global__ void __launch_bounds__(128) k_pq(
    const float* __restrict__ pre_w, const float* __restrict__ pre_b,
    const float* __restrict__ edge_emb, const float* __restrict__ enc_w,
    const float* __restrict__ enc_b, int l) {
    __shared__ float sh[32 * 32];
    int tid = threadIdx.x;
    int t = tid >> 5, o = tid & 31;

    if (blockIdx.x == 0) {
        {
            int a = tid >> 5, f = tid & 31;
            float acc = enc_b[l * 32 + f];
            for (int k = 0; k < 50; k++)
                acc += edge_emb[a * 50 + k] * enc_w[(l * 50 + k) * 32 + f];
            sh[a * 32 + f] = acc;
        }
        __syncthreads();
        float ea[4];
#pragma unroll
        for (int a = 0; a < 4; a++) {
            float acc = pre_b[(l * 4 + t) * 32 + o];
            for (int f = 0; f < 32; f++)
                acc += sh[a * 32 + f] * pre_w[((l * 4 + t) * 96 + 64 + f) * 32 + o];
            ea[a] = acc;
        }
        __syncthreads();
#pragma unroll
        for (int a = 0; a < 4; a++) g_Etab[a * 128 + tid] = ea[a];
        __syncthreads();
    }

    const float* base = pre_w + ((size_t)(l * 4 + t) * 96) * 32 + o;
    u64 wa2[16], wb2[16];
#pragma unroll
    for (int f2 = 0; f2 < 16; f2++) {
        wa2[f2] = pk2(base[(2 * f2) * 32],      base[(2 * f2 + 1) * 32]);
        wb2[f2] = pk2(base[(2 * f2 + 32) * 32], base[(2 * f2 + 33) * 32]);
    }
    int n0 = blockIdx.x * 32;
    for (int idx = tid; idx < 1024; idx += 128) {
        int node = idx >> 5, f = idx & 31;
        int n = n0 + node;
        float v = 0.f;
        if (n < NN) {
            if (l == 0) {
                v = g_H[n * 32 + f];
            } else {
                float ov = g_O[n * 32 + f];
                v = fmaxf(ov * g_bnAB[f] + g_bnAB[32 + f], 0.f);
                g_H[n * 32 + f] = v;
            }
        }
        sh[idx] = v;
    }
    __syncthreads();
    for (int node = 0; node < 32; node++) {
        int n = n0 + node;
        if (n >= NN) break;
        const u64* h2 = (const u64*)&sh[node * 32];
        u64 p2 = 0ull, q2 = 0ull;
#pragma unroll
        for (int f2 = 0; f2 < 16; f2++) {
            u64 h = h2[f2];
            fma2(p2, h, wa2[f2]);
            fma2(q2, h, wb2[f2]);
        }
        float pa, pb, qa, qb;
        upk2(p2, pa, pb);
        upk2(q2, qa, qb);
        g_P[(size_t)n * 128 + tid] = pa + pb;
        g_Q[(size_t)n * 128 + tid] = qa + qb;
    }
}

// packed accumulate of one edge value pair-set
#define ACCP(q, e)                                                        \
    {                                                                     \
        u64 va = (q).x, vb = (q).y;                                       \
        add2(va, (e).x); add2(vb, (e).y);                                 \
        add2(s0, va); add2(s1, vb);                                       \
        fma2(sq0, va, va); fma2(sq1, vb, vb);                             \
        float x0, x1, x2, x3;                                             \
        upk2(va, x0, x1); upk2(vb, x2, x3);                               \
        mnv[0] = fminf(mnv[0], x0); mnv[1] = fminf(mnv[1], x1);           \
        mnv[2] = fminf(mnv[2], x2); mnv[3] = fminf(mnv[3], x3);           \
        mxv[0] = fmaxf(mxv[0], x0); mxv[1] = fmaxf(mxv[1], x1);           \
        mxv[2] = fmaxf(mxv[2], x2); mxv[3] = fmaxf(mxv[3], x3);           \
    }

// One warp per node (8 warps/block): CSR gather (8-wide pipelined) + PNA stats.
// __launch_bounds__(256,3): cap ~85 regs -> 3 blocks/SM (24 warps) for the
// latency-bound gather.
__global__ void __launch_bounds__(256, 3) k_stats() {
    __shared__ ulonglong2 sEt[4][32];
    int warp = threadIdx.x >> 5, lane = threadIdx.x & 31;
    int n = blockIdx.x * 8 + warp;
    if (threadIdx.x < 128) {
        int a = threadIdx.x >> 5, L2 = threadIdx.x & 31;
        sEt[a][L2] = ((const ulonglong2*)g_Etab)[a * 32 + L2];
    }
    __syncthreads();
    if (n >= NN) return;

    int start = g_rowptr[n], end = g_rowptr[n + 1];
    const ulonglong2* Qv = (const ulonglong2*)g_Q;
    u64 s0 = 0, s1 = 0, sq0 = 0, sq1 = 0;
    float mnv[4] = {1e30f, 1e30f, 1e30f, 1e30f};
    float mxv[4] = {-1e30f, -1e30f, -1e30f, -1e30f};
    int i = start;
    for (; i + 8 <= end; i += 8) {
        int pk[8];
#pragma unroll
        for (int j = 0; j < 8; j++) pk[j] = __ldg(&g_pack[i + j]);
        ulonglong2 q[8];
#pragma unroll
        for (int j = 0; j < 8; j++)
            q[j] = __ldg(&Qv[(size_t)(pk[j] & 0xFFFF) * 32 + lane]);
#pragma unroll
        for (int j = 0; j < 8; j++) {
            ulonglong2 e = sEt[pk[j] >> 16][lane];
            ACCP(q[j], e)
        }
    }
    for (; i + 4 <= end; i += 4) {
        int pk[4];
#pragma unroll
        for (int j = 0; j < 4; j++) pk[j] = __ldg(&g_pack[i + j]);
        ulonglong2 q[4];
#pragma unroll
        for (int j = 0; j < 4; j++)
            q[j] = __ldg(&Qv[(size_t)(pk[j] & 0xFFFF) * 32 + lane]);
#pragma unroll
        for (int j = 0; j < 4; j++) {
            ulonglong2 e = sEt[pk[j] >> 16][lane];
            ACCP(q[j], e)
        }
    }
    for (; i < end; i++) {
        int pk = __ldg(&g_pack[i]);
        ulonglong2 q = __ldg(&Qv[(size_t)(pk & 0xFFFF) * 32 + lane]);
        ulonglong2 e = sEt[pk >> 16][lane];
        ACCP(q, e)
    }
    int   deg  = end - start;
    float degf = (float)deg;
    float degc = fmaxf(degf, 1.f);
    float inv  = 1.f / degc;
    float4 p = ((const float4*)g_P)[(size_t)n * 32 + lane];

    float pv[4] = {p.x, p.y, p.z, p.w};
    float sv[4], qv[4];
    upk2(s0, sv[0], sv[1]); upk2(s1, sv[2], sv[3]);
    upk2(sq0, qv[0], qv[1]); upk2(sq1, qv[2], qv[3]);
    float4 st0, st1, st2, st3;
    float* o0 = (float*)&st0; float* o1 = (float*)&st1;
    float* o2 = (float*)&st2; float* o3 = (float*)&st3;
#pragma unroll
    for (int k = 0; k < 4; k++) {
        float mean = (degf * pv[k] + sv[k]) * inv;
        float msq  = (degf * pv[k] * pv[k] + 2.f * pv[k] * sv[k] + qv[k]) * inv;
        float var  = fmaxf(msq - mean * mean, 0.f) + 1e-5f;
        o0[k] = mean;
        o1[k] = (deg > 0) ? pv[k] + mnv[k] : 0.f;
        o2[k] = (deg > 0) ? pv[k] + mxv[k] : 0.f;
        o3[k] = sqrtf(var);
    }
    size_t base = (size_t)n * 512 + (size_t)((lane >> 3) * 128 + (lane & 7) * 4);
    *(float4*)&g_AGG[base]       = st0;
    *(float4*)&g_AGG[base + 32]  = st1;
    *(float4*)&g_AGG[base + 64]  = st2;
    *(float4*)&g_AGG[base + 96]  = st3;
}

// ---------------- tower-split post-MLP with coalesced smem staging ----------------
__global__ void __launch_bounds__(256) k_mlpt(
    const float* __restrict__ post_w, const float* __restrict__ post_b,
    const float* __restrict__ adl_p, int l) {
    __shared__ float sW[3072];             // 12KB  [r(128)][m(3)][c(8)]
    __shared__ float sWh[256];             // 1KB   [f(32)][c(8)]
    __shared__ float sSt[256 * MT_PAD];    // 33.8KB staging (stride-33)
    int tid = threadIdx.x;
    int t = blockIdx.x & 3, chunk = blockIdx.x >> 2;
    const float* pw = post_w + (size_t)(l * 4 + t) * 416 * 8;
    for (int idx = tid; idx < 3072; idx += 256) {
        int c  = idx & 7;
        int rm = idx >> 3;
        int m  = rm % 3;
        int r  = rm / 3;
        sW[idx] = pw[(size_t)(32 + m * 128 + r) * 8 + c];
    }
    sWh[tid] = pw[tid];
    int nbase = chunk * 256;
    int n = nbase + tid;
    bool valid = (n < NN);

    u64 y1[4] = {0, 0, 0, 0}, y2[4] = {0, 0, 0, 0}, y3[4] = {0, 0, 0, 0};

    for (int c = 0; c < 4; c++) {
        __syncthreads();
        for (int idx = tid; idx < 2048; idx += 256) {
            int node = idx >> 3, k4 = idx & 7;
            int gn = nbase + node;
            float4 v = (gn < NN)
                ? __ldg((const float4*)(g_AGG + (size_t)gn * 512 + t * 128 + c * 32 + k4 * 4))
                : make_float4(0.f, 0.f, 0.f, 0.f);
            float* d = &sSt[node * MT_PAD + k4 * 4];
            d[0] = v.x; d[1] = v.y; d[2] = v.z; d[3] = v.w;
        }
        __syncthreads();
        if (valid) {
            const float* arow = &sSt[tid * MT_PAD];
#pragma unroll
            for (int k = 0; k < 32; k++) {
                float a = arow[k];
                u64 a2 = pk2(a, a);
                const u64* wb = (const u64*)&sW[(c * 32 + k) * 24];
#pragma unroll
                for (int cc = 0; cc < 4; cc++) {
                    fma2(y1[cc], a2, wb[cc]);
                    fma2(y2[cc], a2, wb[4 + cc]);
                    fma2(y3[cc], a2, wb[8 + cc]);
                }
            }
        }
    }

    __syncthreads();
    for (int idx = tid; idx < 2048; idx += 256) {
        int node = idx >> 3, k4 = idx & 7;
        int gn = nbase + node;
        float4 v = (gn < NN)
            ? __ldg((const float4*)(g_H + (size_t)gn * 32 + k4 * 4))
            : make_float4(0.f, 0.f, 0.f, 0.f);
        float* d = &sSt[node * MT_PAD + k4 * 4];
        d[0] = v.x; d[1] = v.y; d[2] = v.z; d[3] = v.w;
    }
    __syncthreads();
    if (!valid) return;

    u64 ob[4];
#pragma unroll
    for (int c = 0; c < 4; c++)
        ob[c] = __ldg((const u64*)&post_b[(l * 4 + t) * 8 + c * 2]);
    {
        const float* hrow = &sSt[tid * MT_PAD];
        const u64* wh = (const u64*)sWh;
#pragma unroll
        for (int f = 0; f < 32; f++) {
            float hv = hrow[f];
            u64 h2 = pk2(hv, hv);
#pragma unroll
            for (int c = 0; c < 4; c++) fma2(ob[c], h2, wh[f * 4 + c]);
        }
    }

    int deg = g_rowptr[n + 1] - g_rowptr[n];
    float degc = fmaxf((float)deg, 1.f);
    float adl  = __ldg(adl_p);
    float logd = logf(degc + 1.f);
    float amp  = logd / adl;
    float att  = adl / logd;
    u64 amp2 = pk2(amp, amp), att2 = pk2(att, att);
#pragma unroll
    for (int c = 0; c < 4; c++) {
        fma2(y1[c], amp2, y2[c]);
        fma2(y1[c], att2, y3[c]);
        add2(ob[c], y1[c]);
    }
    u64* orow = (u64*)(g_OT + (size_t)n * 32 + t * 8);
#pragma unroll
    for (int c = 0; c < 4; c++) orow[c] = ob[c];
}

// ---------------- lin + BN-stats + BN-finalize ----------------
__global__ void __launch_bounds__(256) k_lin(
    const float* __restrict__ lin_w, const float* __restrict__ lin_b,
    const float* __restrict__ bn_g,  const float* __restrict__ bn_b, int l) {
    __shared__ float sLW[1024];
    __shared__ float sacc[64];
    __shared__ int sflag;
    int tid = threadIdx.x;
    int lane = tid & 31;
    for (int idx = tid; idx < 1024; idx += 256) sLW[idx] = lin_w[l * 1024 + idx];
    if (tid < 64) sacc[tid] = 0.f;
    __syncthreads();

    int n = blockIdx.x * 256 + tid;
    bool valid = (n < NN);
    u64 acc[16];
#pragma unroll
    for (int j = 0; j < 16; j++) acc[j] = 0ull;

    if (valid) {
        float o32[32];
        const float4* orow = (const float4*)(g_OT + (size_t)n * 32);
#pragma unroll
        for (int j = 0; j < 8; j++) {
            float4 v = __ldg(&orow[j]);
            o32[j * 4] = v.x; o32[j * 4 + 1] = v.y; o32[j * 4 + 2] = v.z; o32[j * 4 + 3] = v.w;
        }
        const float* lb = lin_b + l * 32;
#pragma unroll
        for (int j = 0; j < 16; j++) acc[j] = __ldg((const u64*)&lb[j * 2]);
#pragma unroll 8
        for (int c = 0; c < 32; c++) {
            u64 v2 = pk2(o32[c], o32[c]);
            const u64* wr = (const u64*)&sLW[c * 32];
#pragma unroll
            for (int j = 0; j < 16; j++) fma2(acc[j], v2, wr[j]);
        }
        u64* out = (u64*)(g_O + (size_t)n * 32);
#pragma unroll
        for (int j = 0; j < 16; j++) out[j] = acc[j];
    }

    // BN partials
#pragma unroll
    for (int j = 0; j < 16; j++) {
        float a0, a1; upk2(acc[j], a0, a1);
        float s1 = a0, s2 = a0 * a0, s3 = a1, s4 = a1 * a1;
#pragma unroll
        for (int off = 16; off; off >>= 1) {
            s1 += __shfl_xor_sync(0xffffffffu, s1, off);
            s2 += __shfl_xor_sync(0xffffffffu, s2, off);
            s3 += __shfl_xor_sync(0xffffffffu, s3, off);
            s4 += __shfl_xor_sync(0xffffffffu, s4, off);
        }
        if (lane == 0) {
            atomicAdd(&sacc[2 * j], s1);
            atomicAdd(&sacc[32 + 2 * j], s2);
            atomicAdd(&sacc[2 * j + 1], s3);
            atomicAdd(&sacc[32 + 2 * j + 1], s4);
        }
    }
    __syncthreads();
    if (tid < 64) atomicAdd(&g_bnacc[tid], sacc[tid]);
    __threadfence();
    if (tid == 0) sflag = (atomicAdd(&g_done, 1) == (int)gridDim.x - 1);
    __syncthreads();
    if (sflag) {
        if (tid < 32) {
            float sum = atomicAdd(&g_bnacc[tid], 0.f);
            float sq  = atomicAdd(&g_bnacc[32 + tid], 0.f);
            float mu  = sum / (float)NN;
            float var = sq / (float)NN - mu * mu;
            float istd = rsqrtf(var + 1e-5f);
            float A = __ldg(&bn_g[l * 32 + tid]) * istd;
            float B = __ldg(&bn_b[l * 32 + tid]) - mu * A;
            g_bnAB[tid]      = A;
            g_bnAB[32 + tid] = B;
            g_bnacc[tid]      = 0.f;
            g_bnacc[32 + tid] = 0.f;
        }
        if (tid == 0) g_done = 0;
    }
}

// ---------------- readout ----------------
__global__ void k_pool(const int* __restrict__ batch) {
    int i = blockIdx.x * blockDim.x + threadIdx.x;
    if (i >= NN * 32) return;
    int n = i >> 5, c = i & 31;
    float v = fmaxf(g_O[i] * g_bnAB[c] + g_bnAB[32 + c], 0.f);
    atomicAdd(&g_pool[batch[n] * 32 + c], v);
}

__global__ void k_final(const float* __restrict__ w1, const float* __restrict__ b1,
                        const float* __restrict__ w2, const float* __restrict__ b2,
                        const float* __restrict__ w3, const float* __restrict__ b3,
                        float* __restrict__ out) {
    __shared__ float sg[32], s1[50], s2[25];
    int g = blockIdx.x, t = threadIdx.x;
    if (t < 32) sg[t] = g_pool[g * 32 + t];
    __syncthreads();
    if (t < 50) {
        float a = b1[t];
        for (int c = 0; c < 32; c++) a += sg[c] * w1[c * 50 + t];
        s1[t] = fmaxf(a, 0.f);
    }
    __syncthreads();
    if (t < 25) {
        float a = b2[t];
        for (int j = 0; j < 50; j++) a += s1[j] * w2[j * 25 + t];
        s2[t] = fmaxf(a, 0.f);
    }
    __syncthreads();
    if (t == 0) {
        float a = b3[0];
        for (int k = 0; k < 25; k++) a += s2[k] * w3[k];
        out[g] = a;
    }
}

// ---------------- launch ----------------
extern "C" void kernel_launch(void* const* d_in, const int* in_sizes, int n_in,
                              void* d_out, int out_size) {
    const int*   x        = (const int*)d_in[0];
    const int*   ei       = (const int*)d_in[1];
    const int*   eattr    = (const int*)d_in[2];
    const int*   batch    = (const int*)d_in[3];
    const float* node_emb = (const float*)d_in[4];
    const float* edge_emb = (const float*)d_in[5];
    const float* enc_w    = (const float*)d_in[6];
    const float* enc_b    = (const float*)d_in[7];
    const float* pre_w    = (const float*)d_in[8];
    const float* pre_b    = (const float*)d_in[9];
    const float* post_w   = (const float*)d_in[10];
    const float* post_b   = (const float*)d_in[11];
    const float* lin_w    = (const float*)d_in[12];
    const float* lin_b    = (const float*)d_in[13];
    const float* bn_g     = (const float*)d_in[14];
    const float* bn_b     = (const float*)d_in[15];
    const float* mlp_w1   = (const float*)d_in[16];
    const float* mlp_b1   = (const float*)d_in[17];
    const float* mlp_w2   = (const float*)d_in[18];
    const float* mlp_b2   = (const float*)d_in[19];
    const float* mlp_w3   = (const float*)d_in[20];
    const float* mlp_b3   = (const float*)d_in[21];
    const float* adl      = (const float*)d_in[22];
    float* out = (float*)d_out;

    int gE   = (EE + 255) / 256;
    int gN32 = (NN * 32 + 255) / 256;

    k_hinit<<<gN32, 256>>>(x, node_emb);                               // #1
    k_count<<<gE, 256>>>(ei);                                          // #2
    k_scan<<<1, 1024>>>();                                             // #3
    k_pq<<<NB_PQ, 128>>>(pre_w, pre_b, edge_emb, enc_w, enc_b, 0);     // #4 (profiled)
    k_scatter<<<gE, 256>>>(ei, eattr);                                 // #5
    k_stats<<<NB_AGG, 256>>>();                                        // #6
    k_mlpt<<<NB_MT, 256>>>(post_w, post_b, adl, 0);                    // #7
    k_lin<<<NB_MLP, 256>>>(lin_w, lin_b, bn_g, bn_b, 0);               // #8
    for (int l = 1; l < 4; l++) {
        k_pq<<<NB_PQ, 128>>>(pre_w, pre_b, edge_emb, enc_w, enc_b, l);
        k_stats<<<NB_AGG, 256>>>();
        k_mlpt<<<NB_MT, 256>>>(post_w, post_b, adl, l);
        k_lin<<<NB_MLP, 256>>>(lin_w, lin_b, bn_g, bn_b, l);
    }
    k_pool<<<gN32, 256>>>(batch);
    k_final<<<GG, 64>>>(mlp_w1, mlp_b1, mlp_w2, mlp_b2, mlp_w3, mlp_b3, out);
}

// round 16
// speedup vs baseline: 1.0540x; 1.0540x over previous
#include <cuda_runtime.h>
#include <math.h>

#define NN 50000
#define EE 800000
#define GG 256
#define NB_AGG 6250   /* ceil(NN/8)    */
#define NB1    49     /* ceil(NN/1024) */
#define NB_MLP 196    /* ceil(NN/256)  */
#define NB_MT  784    /* 196 * 4 towers */
#define NB_PQ  1563   /* ceil(NN/32)   */
#define MT_PAD 33

typedef unsigned long long u64;

// ---- packed f32x2 helpers ----
__device__ __forceinline__ u64 pk2(float lo, float hi) {
    u64 r; asm("mov.b64 %0, {%1, %2};" : "=l"(r) : "f"(lo), "f"(hi)); return r;
}
__device__ __forceinline__ void upk2(u64 v, float& lo, float& hi) {
    asm("mov.b64 {%0, %1}, %2;" : "=f"(lo), "=f"(hi) : "l"(v));
}
__device__ __forceinline__ void fma2(u64& d, u64 a, u64 b) {
    asm("fma.rn.f32x2 %0, %1, %2, %0;" : "+l"(d) : "l"(a), "l"(b));
}
__device__ __forceinline__ void add2(u64& d, u64 a) {
    asm("add.rn.f32x2 %0, %1, %0;" : "+l"(d) : "l"(a));
}

// ---------------- device scratch ----------------
__device__ float g_H[NN * 32];
__device__ float g_O[NN * 32];
__device__ float g_OT[NN * 32];      // tower-output staging (pre-lin)
__device__ float g_P[NN * 128];
__device__ float g_Q[NN * 128];
__device__ float g_AGG[(size_t)NN * 512];
__device__ float g_Etab[4 * 128];
__device__ int   g_cnt[NN];          // statically zero; self-restored by k_scan
__device__ int   g_rowptr[NN + 1];
__device__ int   g_cursor[NN];
__device__ int   g_pack[EE];
__device__ float g_bnacc[64];        // statically zero; self-restored by k_lin
__device__ float g_bnAB[64];
__device__ float g_pool[GG * 32];    // zeroed by k_scan each run
__device__ int   g_done;             // statically zero; self-restored by k_lin

// ---------------- setup kernels ----------------
__global__ void k_hinit(const int* __restrict__ x, const float* __restrict__ node_emb) {
    int i = blockIdx.x * blockDim.x + threadIdx.x;
    if (i >= NN * 32) return;
    int n = i >> 5, f = i & 31;
    g_H[i] = node_emb[x[n] * 32 + f];
}

__global__ void k_count(const int* __restrict__ ei) {
    int e = blockIdx.x * blockDim.x + threadIdx.x;
    if (e < EE) atomicAdd(&g_cnt[ei[EE + e]], 1);
}

// single-block shuffle scan over 49 chunks; zeroes cnt (for next replay) + pool
__global__ void __launch_bounds__(1024) k_scan() {
    __shared__ int swarp[32];
    __shared__ int s_carry;
    int t = threadIdx.x, lane = t & 31, wid = t >> 5;
    if (t == 0) s_carry = 0;
    for (int i = t; i < GG * 32; i += 1024) g_pool[i] = 0.f;
    __syncthreads();
    for (int chunk = 0; chunk < NB1; chunk++) {
        int i = chunk * 1024 + t;
        int v = (i < NN) ? g_cnt[i] : 0;
        if (i < NN) g_cnt[i] = 0;
        int x = v;
#pragma unroll
        for (int off = 1; off < 32; off <<= 1) {
            int y = __shfl_up_sync(0xffffffffu, x, off);
            if (lane >= off) x += y;
        }
        if (lane == 31) swarp[wid] = x;
        __syncthreads();
        if (wid == 0) {
            int w = swarp[lane];
#pragma unroll
            for (int off = 1; off < 32; off <<= 1) {
                int y = __shfl_up_sync(0xffffffffu, w, off);
                if (lane >= off) w += y;
            }
            swarp[lane] = w;
        }
        __syncthreads();
        int excl = s_carry + (wid ? swarp[wid - 1] : 0) + x - v;
        if (i < NN) { g_rowptr[i] = excl; g_cursor[i] = excl; }
        __syncthreads();
        if (t == 1023) s_carry += swarp[31];
        __syncthreads();
    }
    if (t == 0) g_rowptr[NN] = EE;
}

__global__ void k_scatter(const int* __restrict__ ei, const int* __restrict__ eattr) {
    int e = blockIdx.x * blockDim.x + threadIdx.x;
    if (e >= EE) return;
    int src = ei[e];
    int dst = ei[EE + e];
    int at  = eattr[e];
    int pos = atomicAdd(&g_cursor[dst], 1);
    g_pack[pos] = src | (at << 16);
}

// ---------------- per-layer kernels ----------------
// k_pq: (block0: Etab) + (all blocks: BN-apply+relu of prev g_O -> h, P=h@A, Q=h@B)
__global__ void __launch_bounds__(128) k_pq(
    const float* __restrict__ pre_w, const float* __restrict__ pre_b,
    const float* __restrict__ edge_emb, const float* __restrict__ enc_w,
    const float* __restrict__ enc_b, int l) {
    __shared__ float sh[32 * 32];
    int tid = threadIdx.x;
    int t = tid >> 5, o = tid & 31;

    if (blockIdx.x == 0) {
        {
            int a = tid >> 5, f = tid & 31;
            float acc = enc_b[l * 32 + f];
            for (int k = 0; k < 50; k++)
                acc += edge_emb[a * 50 + k] * enc_w[(l * 50 + k) * 32 + f];
            sh[a * 32 + f] = acc;
        }
        __syncthreads();
        float ea[4];
#pragma unroll
        for (int a = 0; a < 4; a++) {
            float acc = pre_b[(l * 4 + t) * 32 + o];
            for (int f = 0; f < 32; f++)
                acc += sh[a * 32 + f] * pre_w[((l * 4 + t) * 96 + 64 + f) * 32 + o];
            ea[a] = acc;
        }
        __syncthreads();
#pragma unroll
        for (int a = 0; a < 4; a++) g_Etab[a * 128 + tid] = ea[a];
        __syncthreads();
    }

    const float* base = pre_w + ((size_t)(l * 4 + t) * 96) * 32 + o;
    u64 wa2[16], wb2[16];
#pragma unroll
    for (int f2 = 0; f2 < 16; f2++) {
        wa2[f2] = pk2(base[(2 * f2) * 32],      base[(2 * f2 + 1) * 32]);
        wb2[f2] = pk2(base[(2 * f2 + 32) * 32], base[(2 * f2 + 33) * 32]);
    }
    int n0 = blockIdx.x * 32;
    for (int idx = tid; idx < 1024; idx += 128) {
        int node = idx >> 5, f = idx & 31;
        int n = n0 + node;
        float v = 0.f;
        if (n < NN) {
            if (l == 0) {
                v = g_H[n * 32 + f];
            } else {
                float ov = g_O[n * 32 + f];
                v = fmaxf(ov * g_bnAB[f] + g_bnAB[32 + f], 0.f);
                g_H[n * 32 + f] = v;
            }
        }
        sh[idx] = v;
    }
    __syncthreads();
    for (int node = 0; node < 32; node++) {
        int n = n0 + node;
        if (n >= NN) break;
        const u64* h2 = (const u64*)&sh[node * 32];
        u64 p2 = 0ull, q2 = 0ull;
#pragma unroll
        for (int f2 = 0; f2 < 16; f2++) {
            u64 h = h2[f2];
            fma2(p2, h, wa2[f2]);
            fma2(q2, h, wb2[f2]);
        }
        float pa, pb, qa, qb;
        upk2(p2, pa, pb);
        upk2(q2, qa, qb);
        g_P[(size_t)n * 128 + tid] = pa + pb;
        g_Q[(size_t)n * 128 + tid] = qa + qb;
    }
}

// packed accumulate of one edge value pair-set
#define ACCP(q, e)                                                        \
    {                                                                     \
        u64 va = (q).x, vb = (q).y;                                       \
        add2(va, (e).x); add2(vb, (e).y);                                 \
        add2(s0, va); add2(s1, vb);                                       \
        fma2(sq0, va, va); fma2(sq1, vb, vb);                             \
        float x0, x1, x2, x3;                                             \
        upk2(va, x0, x1); upk2(vb, x2, x3);                               \
        mnv[0] = fminf(mnv[0], x0); mnv[1] = fminf(mnv[1], x1);           \
        mnv[2] = fminf(mnv[2], x2); mnv[3] = fminf(mnv[3], x3);           \
        mxv[0] = fmaxf(mxv[0], x0); mxv[1] = fmaxf(mxv[1], x1);           \
        mxv[2] = fmaxf(mxv[2], x2); mxv[3] = fmaxf(mxv[3], x3);           \
    }

// One warp per node (8 warps/block): CSR gather (8-wide pipelined) + PNA stats.
// AGG written with streaming stores (.cs) so the 102MB write stream does not
// evict the L2-resident Q (25.6MB) mid-kernel.
__global__ void __launch_bounds__(256) k_stats() {
    __shared__ ulonglong2 sEt[4][32];
    int warp = threadIdx.x >> 5, lane = threadIdx.x & 31;
    int n = blockIdx.x * 8 + warp;
    if (threadIdx.x < 128) {
        int a = threadIdx.x >> 5, L2 = threadIdx.x & 31;
        sEt[a][L2] = ((const ulonglong2*)g_Etab)[a * 32 + L2];
    }
    __syncthreads();
    if (n >= NN) return;

    int start = g_rowptr[n], end = g_rowptr[n + 1];
    const ulonglong2* Qv = (const ulonglong2*)g_Q;
    u64 s0 = 0, s1 = 0, sq0 = 0, sq1 = 0;
    float mnv[4] = {1e30f, 1e30f, 1e30f, 1e30f};
    float mxv[4] = {-1e30f, -1e30f, -1e30f, -1e30f};
    int i = start;
    for (; i + 8 <= end; i += 8) {
        int pk[8];
#pragma unroll
        for (int j = 0; j < 8; j++) pk[j] = __ldg(&g_pack[i + j]);
        ulonglong2 q[8];
#pragma unroll
        for (int j = 0; j < 8; j++)
            q[j] = __ldg(&Qv[(size_t)(pk[j] & 0xFFFF) * 32 + lane]);
#pragma unroll
        for (int j = 0; j < 8; j++) {
            ulonglong2 e = sEt[pk[j] >> 16][lane];
            ACCP(q[j], e)
        }
    }
    for (; i + 4 <= end; i += 4) {
        int pk[4];
#pragma unroll
        for (int j = 0; j < 4; j++) pk[j] = __ldg(&g_pack[i + j]);
        ulonglong2 q[4];
#pragma unroll
        for (int j = 0; j < 4; j++)
            q[j] = __ldg(&Qv[(size_t)(pk[j] & 0xFFFF) * 32 + lane]);
#pragma unroll
        for (int j = 0; j < 4; j++) {
            ulonglong2 e = sEt[pk[j] >> 16][lane];
            ACCP(q[j], e)
        }
    }
    for (; i < end; i++) {
        int pk = __ldg(&g_pack[i]);
        ulonglong2 q = __ldg(&Qv[(size_t)(pk & 0xFFFF) * 32 + lane]);
        ulonglong2 e = sEt[pk >> 16][lane];
        ACCP(q, e)
    }
    int   deg  = end - start;
    float degf = (float)deg;
    float degc = fmaxf(degf, 1.f);
    float inv  = 1.f / degc;
    float4 p = ((const float4*)g_P)[(size_t)n * 32 + lane];

    float pv[4] = {p.x, p.y, p.z, p.w};
    float sv[4], qv[4];
    upk2(s0, sv[0], sv[1]); upk2(s1, sv[2], sv[3]);
    upk2(sq0, qv[0], qv[1]); upk2(sq1, qv[2], qv[3]);
    float4 st0, st1, st2, st3;
    float* o0 = (float*)&st0; float* o1 = (float*)&st1;
    float* o2 = (float*)&st2; float* o3 = (float*)&st3;
#pragma unroll
    for (int k = 0; k < 4; k++) {
        float mean = (degf * pv[k] + sv[k]) * inv;
        float msq  = (degf * pv[k] * pv[k] + 2.f * pv[k] * sv[k] + qv[k]) * inv;
        float var  = fmaxf(msq - mean * mean, 0.f) + 1e-5f;
        o0[k] = mean;
        o1[k] = (deg > 0) ? pv[k] + mnv[k] : 0.f;
        o2[k] = (deg > 0) ? pv[k] + mxv[k] : 0.f;
        o3[k] = sqrtf(var);
    }
    size_t base = (size_t)n * 512 + (size_t)((lane >> 3) * 128 + (lane & 7) * 4);
    __stcs((float4*)&g_AGG[base],      st0);
    __stcs((float4*)&g_AGG[base + 32], st1);
    __stcs((float4*)&g_AGG[base + 64], st2);
    __stcs((float4*)&g_AGG[base + 96], st3);
}

// ---------------- tower-split post-MLP with coalesced smem staging ----------------
__global__ void __launch_bounds__(256) k_mlpt(
    const float* __restrict__ post_w, const float* __restrict__ post_b,
    const float* __restrict__ adl_p, int l) {
    __shared__ float sW[3072];             // 12KB  [r(128)][m(3)][c(8)]
    __shared__ float sWh[256];             // 1KB   [f(32)][c(8)]
    __shared__ float sSt[256 * MT_PAD];    // 33.8KB staging (stride-33)
    int tid = threadIdx.x;
    int t = blockIdx.x & 3, chunk = blockIdx.x >> 2;
    const float* pw = post_w + (size_t)(l * 4 + t) * 416 * 8;
    for (int idx = tid; idx < 3072; idx += 256) {
        int c  = idx & 7;
        int rm = idx >> 3;
        int m  = rm % 3;
        int r  = rm / 3;
        sW[idx] = pw[(size_t)(32 + m * 128 + r) * 8 + c];
    }
    sWh[tid] = pw[tid];
    int nbase = chunk * 256;
    int n = nbase + tid;
    bool valid = (n < NN);

    u64 y1[4] = {0, 0, 0, 0}, y2[4] = {0, 0, 0, 0}, y3[4] = {0, 0, 0, 0};

    for (int c = 0; c < 4; c++) {
        __syncthreads();
        for (int idx = tid; idx < 2048; idx += 256) {
            int node = idx >> 3, k4 = idx & 7;
            int gn = nbase + node;
            float4 v = (gn < NN)
                ? __ldcs((const float4*)(g_AGG + (size_t)gn * 512 + t * 128 + c * 32 + k4 * 4))
                : make_float4(0.f, 0.f, 0.f, 0.f);
            float* d = &sSt[node * MT_PAD + k4 * 4];
            d[0] = v.x; d[1] = v.y; d[2] = v.z; d[3] = v.w;
        }
        __syncthreads();
        if (valid) {
            const float* arow = &sSt[tid * MT_PAD];
#pragma unroll
            for (int k = 0; k < 32; k++) {
                float a = arow[k];
                u64 a2 = pk2(a, a);
                const u64* wb = (const u64*)&sW[(c * 32 + k) * 24];
#pragma unroll
                for (int cc = 0; cc < 4; cc++) {
                    fma2(y1[cc], a2, wb[cc]);
                    fma2(y2[cc], a2, wb[4 + cc]);
                    fma2(y3[cc], a2, wb[8 + cc]);
                }
            }
        }
    }

    __syncthreads();
    for (int idx = tid; idx < 2048; idx += 256) {
        int node = idx >> 3, k4 = idx & 7;
        int gn = nbase + node;
        float4 v = (gn < NN)
            ? __ldg((const float4*)(g_H + (size_t)gn * 32 + k4 * 4))
            : make_float4(0.f, 0.f, 0.f, 0.f);
        float* d = &sSt[node * MT_PAD + k4 * 4];
        d[0] = v.x; d[1] = v.y; d[2] = v.z; d[3] = v.w;
    }
    __syncthreads();
    if (!valid) return;

    u64 ob[4];
#pragma unroll
    for (int c = 0; c < 4; c++)
        ob[c] = __ldg((const u64*)&post_b[(l * 4 + t) * 8 + c * 2]);
    {
        const float* hrow = &sSt[tid * MT_PAD];
        const u64* wh = (const u64*)sWh;
#pragma unroll
        for (int f = 0; f < 32; f++) {
            float hv = hrow[f];
            u64 h2 = pk2(hv, hv);
#pragma unroll
            for (int c = 0; c < 4; c++) fma2(ob[c], h2, wh[f * 4 + c]);
        }
    }

    int deg = g_rowptr[n + 1] - g_rowptr[n];
    float degc = fmaxf((float)deg, 1.f);
    float adl  = __ldg(adl_p);
    float logd = logf(degc + 1.f);
    float amp  = logd / adl;
    float att  = adl / logd;
    u64 amp2 = pk2(amp, amp), att2 = pk2(att, att);
#pragma unroll
    for (int c = 0; c < 4; c++) {
        fma2(y1[c], amp2, y2[c]);
        fma2(y1[c], att2, y3[c]);
        add2(ob[c], y1[c]);
    }
    u64* orow = (u64*)(g_OT + (size_t)n * 32 + t * 8);
#pragma unroll
    for (int c = 0; c < 4; c++) orow[c] = ob[c];
}

// ---------------- lin + BN-stats + BN-finalize ----------------
__global__ void __launch_bounds__(256) k_lin(
    const float* __restrict__ lin_w, const float* __restrict__ lin_b,
    const float* __restrict__ bn_g,  const float* __restrict__ bn_b, int l) {
    __shared__ float sLW[1024];
    __shared__ float sacc[64];
    __shared__ int sflag;
    int tid = threadIdx.x;
    int lane = tid & 31;
    for (int idx = tid; idx < 1024; idx += 256) sLW[idx] = lin_w[l * 1024 + idx];
    if (tid < 64) sacc[tid] = 0.f;
    __syncthreads();

    int n = blockIdx.x * 256 + tid;
    bool valid = (n < NN);
    u64 acc[16];
#pragma unroll
    for (int j = 0; j < 16; j++) acc[j] = 0ull;

    if (valid) {
        float o32[32];
        const float4* orow = (const float4*)(g_OT + (size_t)n * 32);
#pragma unroll
        for (int j = 0; j < 8; j++) {
            float4 v = __ldg(&orow[j]);
            o32[j * 4] = v.x; o32[j * 4 + 1] = v.y; o32[j * 4 + 2] = v.z; o32[j * 4 + 3] = v.w;
        }
        const float* lb = lin_b + l * 32;
#pragma unroll
        for (int j = 0; j < 16; j++) acc[j] = __ldg((const u64*)&lb[j * 2]);
#pragma unroll 8
        for (int c = 0; c < 32; c++) {
            u64 v2 = pk2(o32[c], o32[c]);
            const u64* wr = (const u64*)&sLW[c * 32];
#pragma unroll
            for (int j = 0; j < 16; j++) fma2(acc[j], v2, wr[j]);
        }
        u64* out = (u64*)(g_O + (size_t)n * 32);
#pragma unroll
        for (int j = 0; j < 16; j++) out[j] = acc[j];
    }

    // BN partials
#pragma unroll
    for (int j = 0; j < 16; j++) {
        float a0, a1; upk2(acc[j], a0, a1);
        float s1 = a0, s2 = a0 * a0, s3 = a1, s4 = a1 * a1;
#pragma unroll
        for (int off = 16; off; off >>= 1) {
            s1 += __shfl_xor_sync(0xffffffffu, s1, off);
            s2 += __shfl_xor_sync(0xffffffffu, s2, off);
            s3 += __shfl_xor_sync(0xffffffffu, s3, off);
            s4 += __shfl_xor_sync(0xffffffffu, s4, off);
        }
        if (lane == 0) {
            atomicAdd(&sacc[2 * j], s1);
            atomicAdd(&sacc[32 + 2 * j], s2);
            atomicAdd(&sacc[2 * j + 1], s3);
            atomicAdd(&sacc[32 + 2 * j + 1], s4);
        }
    }
    __syncthreads();
    if (tid < 64) atomicAdd(&g_bnacc[tid], sacc[tid]);
    __threadfence();
    if (tid == 0) sflag = (atomicAdd(&g_done, 1) == (int)gridDim.x - 1);
    __syncthreads();
    if (sflag) {
        if (tid < 32) {
            float sum = atomicAdd(&g_bnacc[tid], 0.f);
            float sq  = atomicAdd(&g_bnacc[32 + tid], 0.f);
            float mu  = sum / (float)NN;
            float var = sq / (float)NN - mu * mu;
            float istd = rsqrtf(var + 1e-5f);
            float A = __ldg(&bn_g[l * 32 + tid]) * istd;
            float B = __ldg(&bn_b[l * 32 + tid]) - mu * A;
            g_bnAB[tid]      = A;
            g_bnAB[32 + tid] = B;
            g_bnacc[tid]      = 0.f;
            g_bnacc[32 + tid] = 0.f;
        }
        if (tid == 0) g_done = 0;
    }
}

// ---------------- readout ----------------
__global__ void k_pool(const int* __restrict__ batch) {
    int i = blockIdx.x * blockDim.x + threadIdx.x;
    if (i >= NN * 32) return;
    int n = i >> 5, c = i & 31;
    float v = fmaxf(g_O[i] * g_bnAB[c] + g_bnAB[32 + c], 0.f);
    atomicAdd(&g_pool[batch[n] * 32 + c], v);
}

__global__ void k_final(const float* __restrict__ w1, const float* __restrict__ b1,
                        const float* __restrict__ w2, const float* __restrict__ b2,
                        const float* __restrict__ w3, const float* __restrict__ b3,
                        float* __restrict__ out) {
    __shared__ float sg[32], s1[50], s2[25];
    int g = blockIdx.x, t = threadIdx.x;
    if (t < 32) sg[t] = g_pool[g * 32 + t];
    __syncthreads();
    if (t < 50) {
        float a = b1[t];
        for (int c = 0; c < 32; c++) a += sg[c] * w1[c * 50 + t];
        s1[t] = fmaxf(a, 0.f);
    }
    __syncthreads();
    if (t < 25) {
        float a = b2[t];
        for (int j = 0; j < 50; j++) a += s1[j] * w2[j * 25 + t];
        s2[t] = fmaxf(a, 0.f);
    }
    __syncthreads();
    if (t == 0) {
        float a = b3[0];
        for (int k = 0; k < 25; k++) a += s2[k] * w3[k];
        out[g] = a;
    }
}

// ---------------- launch ----------------
extern "C" void kernel_launch(void* const* d_in, const int* in_sizes, int n_in,
                              void* d_out, int out_size) {
    const int*   x        = (const int*)d_in[0];
    const int*   ei       = (const int*)d_in[1];
    const int*   eattr    = (const int*)d_in[2];
    const int*   batch    = (const int*)d_in[3];
    const float* node_emb = (const float*)d_in[4];
    const float* edge_emb = (const float*)d_in[5];
    const float* enc_w    = (const float*)d_in[6];
    const float* enc_b    = (const float*)d_in[7];
    const float* pre_w    = (const float*)d_in[8];
    const float* pre_b    = (const float*)d_in[9];
    const float* post_w   = (const float*)d_in[10];
    const float* post_b   = (const float*)d_in[11];
    const float* lin_w    = (const float*)d_in[12];
    const float* lin_b    = (const float*)d_in[13];
    const float* bn_g     = (const float*)d_in[14];
    const float* bn_b     = (const float*)d_in[15];
    const float* mlp_w1   = (const float*)d_in[16];
    const float* mlp_b1   = (const float*)d_in[17];
    const float* mlp_w2   = (const float*)d_in[18];
    const float* mlp_b2   = (const float*)d_in[19];
    const float* mlp_w3   = (const float*)d_in[20];
    const float* mlp_b3   = (const float*)d_in[21];
    const float* adl      = (const float*)d_in[22];
    float* out = (float*)d_out;

    int gE   = (EE + 255) / 256;
    int gN32 = (NN * 32 + 255) / 256;

    k_hinit<<<gN32, 256>>>(x, node_emb);                               // #1
    k_count<<<gE, 256>>>(ei);                                          // #2
    k_scan<<<1, 1024>>>();                                             // #3
    k_pq<<<NB_PQ, 128>>>(pre_w, pre_b, edge_emb, enc_w, enc_b, 0);     // #4 (profiled)
    k_scatter<<<gE, 256>>>(ei, eattr);                                 // #5
    k_stats<<<NB_AGG, 256>>>();                                        // #6
    k_mlpt<<<NB_MT, 256>>>(post_w, post_b, adl, 0);                    // #7
    k_lin<<<NB_MLP, 256>>>(lin_w, lin_b, bn_g, bn_b, 0);               // #8
    for (int l = 1; l < 4; l++) {
        k_pq<<<NB_PQ, 128>>>(pre_w, pre_b, edge_emb, enc_w, enc_b, l);
        k_stats<<<NB_AGG, 256>>>();
        k_mlpt<<<NB_MT, 256>>>(post_w, post_b, adl, l);
        k_lin<<<NB_MLP, 256>>>(lin_w, lin_b, bn_g, bn_b, l);
    }
    k_pool<<<gN32, 256>>>(batch);
    k_final<<<GG, 64>>>(mlp_w1, mlp_b1, mlp_w2, mlp_b2, mlp_w3, mlp_b3, out);
}

// round 17
// speedup vs baseline: 1.0619x; 1.0075x over previous
#include <cuda_runtime.h>
#include <math.h>

#define NN 50000
#define EE 800000
#define GG 256
#define NB_AGG 6250   /* ceil(NN/8)    */
#define NB1    49     /* ceil(NN/1024) */
#define NB_MLP 196    /* ceil(NN/256)  */
#define NB_MT  784    /* 196 * 4 towers */
#define NB_PQ  1563   /* ceil(NN/32)   */
#define MT_PAD 33

typedef unsigned long long u64;

// ---- packed f32x2 helpers ----
__device__ __forceinline__ u64 pk2(float lo, float hi) {
    u64 r; asm("mov.b64 %0, {%1, %2};" : "=l"(r) : "f"(lo), "f"(hi)); return r;
}
__device__ __forceinline__ void upk2(u64 v, float& lo, float& hi) {
    asm("mov.b64 {%0, %1}, %2;" : "=f"(lo), "=f"(hi) : "l"(v));
}
__device__ __forceinline__ void fma2(u64& d, u64 a, u64 b) {
    asm("fma.rn.f32x2 %0, %1, %2, %0;" : "+l"(d) : "l"(a), "l"(b));
}
__device__ __forceinline__ void add2(u64& d, u64 a) {
    asm("add.rn.f32x2 %0, %1, %0;" : "+l"(d) : "l"(a));
}

// ---------------- device scratch ----------------
__device__ float g_H[NN * 32];
__device__ float g_O[NN * 32];
__device__ float g_OT[NN * 32];      // tower-output staging (pre-lin)
__device__ float g_P[NN * 128];
__device__ float g_Q[NN * 128];
__device__ float g_AGG[(size_t)NN * 512];
__device__ float g_Etab[4 * 128];
__device__ int   g_cnt[NN];          // statically zero; self-restored by k_scan
__device__ int   g_rowptr[NN + 1];
__device__ int   g_cursor[NN];
__device__ int   g_pack[EE];
__device__ float g_bnacc[64];        // statically zero; self-restored by k_lin
__device__ float g_bnAB[64];
__device__ float g_pool[GG * 32];    // zeroed by k_scan each run
__device__ int   g_done;             // statically zero; self-restored by k_lin

// ---------------- setup: hinit + degree count (fused) ----------------
__global__ void k_setup(const int* __restrict__ x, const float* __restrict__ node_emb,
                        const int* __restrict__ ei) {
    int i = blockIdx.x * blockDim.x + threadIdx.x;
    if (i < NN * 32) {
        int n = i >> 5, f = i & 31;
        g_H[i] = node_emb[x[n] * 32 + f];
    }
    if (i < EE) atomicAdd(&g_cnt[ei[EE + i]], 1);
}

// single-block shuffle scan over 49 chunks; zeroes cnt (for next replay) + pool
__global__ void __launch_bounds__(1024) k_scan() {
    __shared__ int swarp[32];
    __shared__ int s_carry;
    int t = threadIdx.x, lane = t & 31, wid = t >> 5;
    if (t == 0) s_carry = 0;
    for (int i = t; i < GG * 32; i += 1024) g_pool[i] = 0.f;
    __syncthreads();
    for (int chunk = 0; chunk < NB1; chunk++) {
        int i = chunk * 1024 + t;
        int v = (i < NN) ? g_cnt[i] : 0;
        if (i < NN) g_cnt[i] = 0;
        int x = v;
#pragma unroll
        for (int off = 1; off < 32; off <<= 1) {
            int y = __shfl_up_sync(0xffffffffu, x, off);
            if (lane >= off) x += y;
        }
        if (lane == 31) swarp[wid] = x;
        __syncthreads();
        if (wid == 0) {
            int w = swarp[lane];
#pragma unroll
            for (int off = 1; off < 32; off <<= 1) {
                int y = __shfl_up_sync(0xffffffffu, w, off);
                if (lane >= off) w += y;
            }
            swarp[lane] = w;
        }
        __syncthreads();
        int excl = s_carry + (wid ? swarp[wid - 1] : 0) + x - v;
        if (i < NN) { g_rowptr[i] = excl; g_cursor[i] = excl; }
        __syncthreads();
        if (t == 1023) s_carry += swarp[31];
        __syncthreads();
    }
    if (t == 0) g_rowptr[NN] = EE;
}

__global__ void k_scatter(const int* __restrict__ ei, const int* __restrict__ eattr) {
    int e = blockIdx.x * blockDim.x + threadIdx.x;
    if (e >= EE) return;
    int src = ei[e];
    int dst = ei[EE + e];
    int at  = eattr[e];
    int pos = atomicAdd(&g_cursor[dst], 1);
    g_pack[pos] = src | (at << 16);
}

// ---------------- per-layer kernels ----------------
// k_pq: (block0: Etab) + (all blocks: BN-apply+relu of prev g_O -> h, P=h@A, Q=h@B)
// 4 independent fma2 chains of depth 8 (was 2 of depth 16) for ILP.
__global__ void __launch_bounds__(128) k_pq(
    const float* __restrict__ pre_w, const float* __restrict__ pre_b,
    const float* __restrict__ edge_emb, const float* __restrict__ enc_w,
    const float* __restrict__ enc_b, int l) {
    __shared__ float sh[32 * 32];
    int tid = threadIdx.x;
    int t = tid >> 5, o = tid & 31;

    if (blockIdx.x == 0) {
        {
            int a = tid >> 5, f = tid & 31;
            float acc = enc_b[l * 32 + f];
            for (int k = 0; k < 50; k++)
                acc += edge_emb[a * 50 + k] * enc_w[(l * 50 + k) * 32 + f];
            sh[a * 32 + f] = acc;
        }
        __syncthreads();
        float ea[4];
#pragma unroll
        for (int a = 0; a < 4; a++) {
            float acc = pre_b[(l * 4 + t) * 32 + o];
            for (int f = 0; f < 32; f++)
                acc += sh[a * 32 + f] * pre_w[((l * 4 + t) * 96 + 64 + f) * 32 + o];
            ea[a] = acc;
        }
        __syncthreads();
#pragma unroll
        for (int a = 0; a < 4; a++) g_Etab[a * 128 + tid] = ea[a];
        __syncthreads();
    }

    const float* base = pre_w + ((size_t)(l * 4 + t) * 96) * 32 + o;
    u64 wa2[16], wb2[16];
#pragma unroll
    for (int f2 = 0; f2 < 16; f2++) {
        wa2[f2] = pk2(base[(2 * f2) * 32],      base[(2 * f2 + 1) * 32]);
        wb2[f2] = pk2(base[(2 * f2 + 32) * 32], base[(2 * f2 + 33) * 32]);
    }
    int n0 = blockIdx.x * 32;
    for (int idx = tid; idx < 1024; idx += 128) {
        int node = idx >> 5, f = idx & 31;
        int n = n0 + node;
        float v = 0.f;
        if (n < NN) {
            if (l == 0) {
                v = g_H[n * 32 + f];
            } else {
                float ov = g_O[n * 32 + f];
                v = fmaxf(ov * g_bnAB[f] + g_bnAB[32 + f], 0.f);
                g_H[n * 32 + f] = v;
            }
        }
        sh[idx] = v;
    }
    __syncthreads();
    for (int node = 0; node < 32; node++) {
        int n = n0 + node;
        if (n >= NN) break;
        const u64* h2 = (const u64*)&sh[node * 32];
        u64 pA = 0ull, pB = 0ull, qA = 0ull, qB = 0ull;
#pragma unroll
        for (int f2 = 0; f2 < 8; f2++) {
            u64 hx = h2[f2];
            u64 hy = h2[f2 + 8];
            fma2(pA, hx, wa2[f2]);
            fma2(pB, hy, wa2[f2 + 8]);
            fma2(qA, hx, wb2[f2]);
            fma2(qB, hy, wb2[f2 + 8]);
        }
        add2(pA, pB);
        add2(qA, qB);
        float pa, pb, qa, qb;
        upk2(pA, pa, pb);
        upk2(qA, qa, qb);
        g_P[(size_t)n * 128 + tid] = pa + pb;
        g_Q[(size_t)n * 128 + tid] = qa + qb;
    }
}

// packed accumulate of one edge value pair-set
#define ACCP(q, e)                                                        \
    {                                                                     \
        u64 va = (q).x, vb = (q).y;                                       \
        add2(va, (e).x); add2(vb, (e).y);                                 \
        add2(s0, va); add2(s1, vb);                                       \
        fma2(sq0, va, va); fma2(sq1, vb, vb);                             \
        float x0, x1, x2, x3;                                             \
        upk2(va, x0, x1); upk2(vb, x2, x3);                               \
        mnv[0] = fminf(mnv[0], x0); mnv[1] = fminf(mnv[1], x1);           \
        mnv[2] = fminf(mnv[2], x2); mnv[3] = fminf(mnv[3], x3);           \
        mxv[0] = fmaxf(mxv[0], x0); mxv[1] = fmaxf(mxv[1], x1);           \
        mxv[2] = fmaxf(mxv[2], x2); mxv[3] = fmaxf(mxv[3], x3);           \
    }

// One warp per node (8 warps/block): CSR gather (8-wide pipelined) + PNA stats.
// AGG written with streaming stores (.cs) to protect L2-resident Q.
__global__ void __launch_bounds__(256) k_stats() {
    __shared__ ulonglong2 sEt[4][32];
    int warp = threadIdx.x >> 5, lane = threadIdx.x & 31;
    int n = blockIdx.x * 8 + warp;
    if (threadIdx.x < 128) {
        int a = threadIdx.x >> 5, L2 = threadIdx.x & 31;
        sEt[a][L2] = ((const ulonglong2*)g_Etab)[a * 32 + L2];
    }
    __syncthreads();
    if (n >= NN) return;

    int start = g_rowptr[n], end = g_rowptr[n + 1];
    const ulonglong2* Qv = (const ulonglong2*)g_Q;
    u64 s0 = 0, s1 = 0, sq0 = 0, sq1 = 0;
    float mnv[4] = {1e30f, 1e30f, 1e30f, 1e30f};
    float mxv[4] = {-1e30f, -1e30f, -1e30f, -1e30f};
    int i = start;
    for (; i + 8 <= end; i += 8) {
        int pk[8];
#pragma unroll
        for (int j = 0; j < 8; j++) pk[j] = __ldg(&g_pack[i + j]);
        ulonglong2 q[8];
#pragma unroll
        for (int j = 0; j < 8; j++)
            q[j] = __ldg(&Qv[(size_t)(pk[j] & 0xFFFF) * 32 + lane]);
#pragma unroll
        for (int j = 0; j < 8; j++) {
            ulonglong2 e = sEt[pk[j] >> 16][lane];
            ACCP(q[j], e)
        }
    }
    for (; i + 4 <= end; i += 4) {
        int pk[4];
#pragma unroll
        for (int j = 0; j < 4; j++) pk[j] = __ldg(&g_pack[i + j]);
        ulonglong2 q[4];
#pragma unroll
        for (int j = 0; j < 4; j++)
            q[j] = __ldg(&Qv[(size_t)(pk[j] & 0xFFFF) * 32 + lane]);
#pragma unroll
        for (int j = 0; j < 4; j++) {
            ulonglong2 e = sEt[pk[j] >> 16][lane];
            ACCP(q[j], e)
        }
    }
    for (; i < end; i++) {
        int pk = __ldg(&g_pack[i]);
        ulonglong2 q = __ldg(&Qv[(size_t)(pk & 0xFFFF) * 32 + lane]);
        ulonglong2 e = sEt[pk >> 16][lane];
        ACCP(q, e)
    }
    int   deg  = end - start;
    float degf = (float)deg;
    float degc = fmaxf(degf, 1.f);
    float inv  = 1.f / degc;
    float4 p = ((const float4*)g_P)[(size_t)n * 32 + lane];

    float pv[4] = {p.x, p.y, p.z, p.w};
    float sv[4], qv[4];
    upk2(s0, sv[0], sv[1]); upk2(s1, sv[2], sv[3]);
    upk2(sq0, qv[0], qv[1]); upk2(sq1, qv[2], qv[3]);
    float4 st0, st1, st2, st3;
    float* o0 = (float*)&st0; float* o1 = (float*)&st1;
    float* o2 = (float*)&st2; float* o3 = (float*)&st3;
#pragma unroll
    for (int k = 0; k < 4; k++) {
        float mean = (degf * pv[k] + sv[k]) * inv;
        float msq  = (degf * pv[k] * pv[k] + 2.f * pv[k] * sv[k] + qv[k]) * inv;
        float var  = fmaxf(msq - mean * mean, 0.f) + 1e-5f;
        o0[k] = mean;
        o1[k] = (deg > 0) ? pv[k] + mnv[k] : 0.f;
        o2[k] = (deg > 0) ? pv[k] + mxv[k] : 0.f;
        o3[k] = sqrtf(var);
    }
    size_t base = (size_t)n * 512 + (size_t)((lane >> 3) * 128 + (lane & 7) * 4);
    __stcs((float4*)&g_AGG[base],      st0);
    __stcs((float4*)&g_AGG[base + 32], st1);
    __stcs((float4*)&g_AGG[base + 64], st2);
    __stcs((float4*)&g_AGG[base + 96], st3);
}

// ---------------- tower-split post-MLP with coalesced smem staging ----------------
__global__ void __launch_bounds__(256) k_mlpt(
    const float* __restrict__ post_w, const float* __restrict__ post_b,
    const float* __restrict__ adl_p, int l) {
    __shared__ float sW[3072];             // 12KB  [r(128)][m(3)][c(8)]
    __shared__ float sWh[256];             // 1KB   [f(32)][c(8)]
    __shared__ float sSt[256 * MT_PAD];    // 33.8KB staging (stride-33)
    int tid = threadIdx.x;
    int t = blockIdx.x & 3, chunk = blockIdx.x >> 2;
    const float* pw = post_w + (size_t)(l * 4 + t) * 416 * 8;
    for (int idx = tid; idx < 3072; idx += 256) {
        int c  = idx & 7;
        int rm = idx >> 3;
        int m  = rm % 3;
        int r  = rm / 3;
        sW[idx] = pw[(size_t)(32 + m * 128 + r) * 8 + c];
    }
    sWh[tid] = pw[tid];
    int nbase = chunk * 256;
    int n = nbase + tid;
    bool valid = (n < NN);

    u64 y1[4] = {0, 0, 0, 0}, y2[4] = {0, 0, 0, 0}, y3[4] = {0, 0, 0, 0};

    for (int c = 0; c < 4; c++) {
        __syncthreads();
        for (int idx = tid; idx < 2048; idx += 256) {
            int node = idx >> 3, k4 = idx & 7;
            int gn = nbase + node;
            float4 v = (gn < NN)
                ? __ldcs((const float4*)(g_AGG + (size_t)gn * 512 + t * 128 + c * 32 + k4 * 4))
                : make_float4(0.f, 0.f, 0.f, 0.f);
            float* d = &sSt[node * MT_PAD + k4 * 4];
            d[0] = v.x; d[1] = v.y; d[2] = v.z; d[3] = v.w;
        }
        __syncthreads();
        if (valid) {
            const float* arow = &sSt[tid * MT_PAD];
#pragma unroll
            for (int k = 0; k < 32; k++) {
                float a = arow[k];
                u64 a2 = pk2(a, a);
                const u64* wb = (const u64*)&sW[(c * 32 + k) * 24];
#pragma unroll
                for (int cc = 0; cc < 4; cc++) {
                    fma2(y1[cc], a2, wb[cc]);
                    fma2(y2[cc], a2, wb[4 + cc]);
                    fma2(y3[cc], a2, wb[8 + cc]);
                }
            }
        }
    }

    __syncthreads();
    for (int idx = tid; idx < 2048; idx += 256) {
        int node = idx >> 3, k4 = idx & 7;
        int gn = nbase + node;
        float4 v = (gn < NN)
            ? __ldg((const float4*)(g_H + (size_t)gn * 32 + k4 * 4))
            : make_float4(0.f, 0.f, 0.f, 0.f);
        float* d = &sSt[node * MT_PAD + k4 * 4];
        d[0] = v.x; d[1] = v.y; d[2] = v.z; d[3] = v.w;
    }
    __syncthreads();
    if (!valid) return;

    u64 ob[4];
#pragma unroll
    for (int c = 0; c < 4; c++)
        ob[c] = __ldg((const u64*)&post_b[(l * 4 + t) * 8 + c * 2]);
    {
        const float* hrow = &sSt[tid * MT_PAD];
        const u64* wh = (const u64*)sWh;
#pragma unroll
        for (int f = 0; f < 32; f++) {
            float hv = hrow[f];
            u64 h2 = pk2(hv, hv);
#pragma unroll
            for (int c = 0; c < 4; c++) fma2(ob[c], h2, wh[f * 4 + c]);
        }
    }

    int deg = g_rowptr[n + 1] - g_rowptr[n];
    float degc = fmaxf((float)deg, 1.f);
    float adl  = __ldg(adl_p);
    float logd = logf(degc + 1.f);
    float amp  = logd / adl;
    float att  = adl / logd;
    u64 amp2 = pk2(amp, amp), att2 = pk2(att, att);
#pragma unroll
    for (int c = 0; c < 4; c++) {
        fma2(y1[c], amp2, y2[c]);
        fma2(y1[c], att2, y3[c]);
        add2(ob[c], y1[c]);
    }
    u64* orow = (u64*)(g_OT + (size_t)n * 32 + t * 8);
#pragma unroll
    for (int c = 0; c < 4; c++) orow[c] = ob[c];
}

// ---------------- lin + BN-stats + BN-finalize ----------------
__global__ void __launch_bounds__(256) k_lin(
    const float* __restrict__ lin_w, const float* __restrict__ lin_b,
    const float* __restrict__ bn_g,  const float* __restrict__ bn_b, int l) {
    __shared__ float sLW[1024];
    __shared__ float sacc[64];
    __shared__ int sflag;
    int tid = threadIdx.x;
    int lane = tid & 31;
    for (int idx = tid; idx < 1024; idx += 256) sLW[idx] = lin_w[l * 1024 + idx];
    if (tid < 64) sacc[tid] = 0.f;
    __syncthreads();

    int n = blockIdx.x * 256 + tid;
    bool valid = (n < NN);
    u64 acc[16];
#pragma unroll
    for (int j = 0; j < 16; j++) acc[j] = 0ull;

    if (valid) {
        float o32[32];
        const float4* orow = (const float4*)(g_OT + (size_t)n * 32);
#pragma unroll
        for (int j = 0; j < 8; j++) {
            float4 v = __ldg(&orow[j]);
            o32[j * 4] = v.x; o32[j * 4 + 1] = v.y; o32[j * 4 + 2] = v.z; o32[j * 4 + 3] = v.w;
        }
        const float* lb = lin_b + l * 32;
#pragma unroll
        for (int j = 0; j < 16; j++) acc[j] = __ldg((const u64*)&lb[j * 2]);
#pragma unroll 8
        for (int c = 0; c < 32; c++) {
            u64 v2 = pk2(o32[c], o32[c]);
            const u64* wr = (const u64*)&sLW[c * 32];
#pragma unroll
            for (int j = 0; j < 16; j++) fma2(acc[j], v2, wr[j]);
        }
        u64* out = (u64*)(g_O + (size_t)n * 32);
#pragma unroll
        for (int j = 0; j < 16; j++) out[j] = acc[j];
    }

    // BN partials
#pragma unroll
    for (int j = 0; j < 16; j++) {
        float a0, a1; upk2(acc[j], a0, a1);
        float s1 = a0, s2 = a0 * a0, s3 = a1, s4 = a1 * a1;
#pragma unroll
        for (int off = 16; off; off >>= 1) {
            s1 += __shfl_xor_sync(0xffffffffu, s1, off);
            s2 += __shfl_xor_sync(0xffffffffu, s2, off);
            s3 += __shfl_xor_sync(0xffffffffu, s3, off);
            s4 += __shfl_xor_sync(0xffffffffu, s4, off);
        }
        if (lane == 0) {
            atomicAdd(&sacc[2 * j], s1);
            atomicAdd(&sacc[32 + 2 * j], s2);
            atomicAdd(&sacc[2 * j + 1], s3);
            atomicAdd(&sacc[32 + 2 * j + 1], s4);
        }
    }
    __syncthreads();
    if (tid < 64) atomicAdd(&g_bnacc[tid], sacc[tid]);
    __threadfence();
    if (tid == 0) sflag = (atomicAdd(&g_done, 1) == (int)gridDim.x - 1);
    __syncthreads();
    if (sflag) {
        if (tid < 32) {
            float sum = atomicAdd(&g_bnacc[tid], 0.f);
            float sq  = atomicAdd(&g_bnacc[32 + tid], 0.f);
            float mu  = sum / (float)NN;
            float var = sq / (float)NN - mu * mu;
            float istd = rsqrtf(var + 1e-5f);
            float A = __ldg(&bn_g[l * 32 + tid]) * istd;
            float B = __ldg(&bn_b[l * 32 + tid]) - mu * A;
            g_bnAB[tid]      = A;
            g_bnAB[32 + tid] = B;
            g_bnacc[tid]      = 0.f;
            g_bnacc[32 + tid] = 0.f;
        }
        if (tid == 0) g_done = 0;
    }
}

// ---------------- readout ----------------
__global__ void k_pool(const int* __restrict__ batch) {
    int i = blockIdx.x * blockDim.x + threadIdx.x;
    if (i >= NN * 32) return;
    int n = i >> 5, c = i & 31;
    float v = fmaxf(g_O[i] * g_bnAB[c] + g_bnAB[32 + c], 0.f);
    atomicAdd(&g_pool[batch[n] * 32 + c], v);
}

__global__ void k_final(const float* __restrict__ w1, const float* __restrict__ b1,
                        const float* __restrict__ w2, const float* __restrict__ b2,
                        const float* __restrict__ w3, const float* __restrict__ b3,
                        float* __restrict__ out) {
    __shared__ float sg[32], s1[50], s2[25];
    int g = blockIdx.x, t = threadIdx.x;
    if (t < 32) sg[t] = g_pool[g * 32 + t];
    __syncthreads();
    if (t < 50) {
        float a = b1[t];
        for (int c = 0; c < 32; c++) a += sg[c] * w1[c * 50 + t];
        s1[t] = fmaxf(a, 0.f);
    }
    __syncthreads();
    if (t < 25) {
        float a = b2[t];
        for (int j = 0; j < 50; j++) a += s1[j] * w2[j * 25 + t];
        s2[t] = fmaxf(a, 0.f);
    }
    __syncthreads();
    if (t == 0) {
        float a = b3[0];
        for (int k = 0; k < 25; k++) a += s2[k] * w3[k];
        out[g] = a;
    }
}

// ---------------- launch ----------------
extern "C" void kernel_launch(void* const* d_in, const int* in_sizes, int n_in,
                              void* d_out, int out_size) {
    const int*   x        = (const int*)d_in[0];
    const int*   ei       = (const int*)d_in[1];
    const int*   eattr    = (const int*)d_in[2];
    const int*   batch    = (const int*)d_in[3];
    const float* node_emb = (const float*)d_in[4];
    const float* edge_emb = (const float*)d_in[5];
    const float* enc_w    = (const float*)d_in[6];
    const float* enc_b    = (const float*)d_in[7];
    const float* pre_w    = (const float*)d_in[8];
    const float* pre_b    = (const float*)d_in[9];
    const float* post_w   = (const float*)d_in[10];
    const float* post_b   = (const float*)d_in[11];
    const float* lin_w    = (const float*)d_in[12];
    const float* lin_b    = (const float*)d_in[13];
    const float* bn_g     = (const float*)d_in[14];
    const float* bn_b     = (const float*)d_in[15];
    const float* mlp_w1   = (const float*)d_in[16];
    const float* mlp_b1   = (const float*)d_in[17];
    const float* mlp_w2   = (const float*)d_in[18];
    const float* mlp_b2   = (const float*)d_in[19];
    const float* mlp_w3   = (const float*)d_in[20];
    const float* mlp_b3   = (const float*)d_in[21];
    const float* adl      = (const float*)d_in[22];
    float* out = (float*)d_out;

    int gE   = (EE + 255) / 256;
    int gN32 = (NN * 32 + 255) / 256;

    k_setup<<<gN32, 256>>>(x, node_emb, ei);                           // #1
    k_scan<<<1, 1024>>>();                                             // #2
    k_scatter<<<gE, 256>>>(ei, eattr);                                 // #3
    k_pq<<<NB_PQ, 128>>>(pre_w, pre_b, edge_emb, enc_w, enc_b, 0);     // #4 (profiled)
    k_stats<<<NB_AGG, 256>>>();                                        // #5
    k_mlpt<<<NB_MT, 256>>>(post_w, post_b, adl, 0);                    // #6
    k_lin<<<NB_MLP, 256>>>(lin_w, lin_b, bn_g, bn_b, 0);               // #7
    for (int l = 1; l < 4; l++) {
        k_pq<<<NB_PQ, 128>>>(pre_w, pre_b, edge_emb, enc_w, enc_b, l);
        k_stats<<<NB_AGG, 256>>>();
        k_mlpt<<<NB_MT, 256>>>(post_w, post_b, adl, l);
        k_lin<<<NB_MLP, 256>>>(lin_w, lin_b, bn_g, bn_b, l);
    }
    k_pool<<<gN32, 256>>>(batch);
    k_final<<<GG, 64>>>(mlp_w1, mlp_b1, mlp_w2, mlp_b2, mlp_w3, mlp_b3, out);
}